// round 12
// baseline (speedup 1.0000x reference)
#include <cuda_runtime.h>
#include <cuda_bf16.h>
#include <cstdint>
#include <cstddef>

#define BB 8
#define NN 2048
#define IND 256
#define DD 64
#define ALPHA 0.2f

// ---------------- device scratch (allocation-free) ----------------
__device__ float g_s1[BB * NN];
__device__ float g_s2[BB * NN];
// hi half at [0, BB*DD*NN), lo half at +BB*DD*NN elements. layout [b][d][j]
__device__ __nv_bfloat16 g_B[(size_t)2 * BB * DD * NN];
#define LOOFF ((size_t)BB * DD * NN * 2)   // byte offset hi -> lo

// ---------------- helpers ----------------
__device__ __forceinline__ uint32_t smem_u32(const void* p) {
    uint32_t a;
    asm("{ .reg .u64 t; cvta.to.shared.u64 t, %1; cvt.u32.u64 %0, t; }"
        : "=r"(a) : "l"(p));
    return a;
}
// pack (first, second) -> bf16x2 with first in LOW half
__device__ __forceinline__ uint32_t bf2(float first, float second) {
    uint32_t r;
    asm("cvt.rn.bf16x2.f32 %0, %1, %2;" : "=r"(r) : "f"(second), "f"(first));
    return r;
}
__device__ __forceinline__ uint32_t sw128(uint32_t off) {
    return off ^ ((off >> 3) & 0x70);
}
__device__ __forceinline__ void ldmx4(uint32_t& r0, uint32_t& r1, uint32_t& r2,
                                      uint32_t& r3, uint32_t addr) {
    asm volatile("ldmatrix.sync.aligned.m8n8.x4.shared.b16 {%0,%1,%2,%3}, [%4];"
                 : "=r"(r0), "=r"(r1), "=r"(r2), "=r"(r3) : "r"(addr));
}
__device__ __forceinline__ void mma16816(float* d, uint32_t a0, uint32_t a1,
                                         uint32_t a2, uint32_t a3, uint32_t b0,
                                         uint32_t b1) {
    asm volatile(
        "mma.sync.aligned.m16n8k16.row.col.f32.bf16.bf16.f32 "
        "{%0,%1,%2,%3}, {%4,%5,%6,%7}, {%8,%9}, {%0,%1,%2,%3};"
        : "+f"(d[0]), "+f"(d[1]), "+f"(d[2]), "+f"(d[3])
        : "r"(a0), "r"(a1), "r"(a2), "r"(a3), "r"(b0), "r"(b1));
}
__device__ __forceinline__ float pe(float e, int m) {
    e = fmaxf(e, ALPHA * e);
    return m ? __expf(e) : 0.f;
}
__device__ __forceinline__ void cpa16(uint32_t dst, const void* src) {
    asm volatile("cp.async.cg.shared.global [%0], [%1], 16;"
                 :: "r"(dst), "l"(src) : "memory");
}
__device__ __forceinline__ void cpa_commit() {
    asm volatile("cp.async.commit_group;" ::: "memory");
}
__device__ __forceinline__ void cpa_wait0() {
    asm volatile("cp.async.wait_group 0;" ::: "memory");
}
__device__ __forceinline__ int2 lds_i2(uint32_t a) {
    int2 v;
    asm volatile("ld.shared.v2.b32 {%0,%1}, [%2];" : "=r"(v.x), "=r"(v.y) : "r"(a));
    return v;
}
__device__ __forceinline__ float2 lds_f2(uint32_t a) {
    float2 v;
    asm volatile("ld.shared.v2.f32 {%0,%1}, [%2];" : "=f"(v.x), "=f"(v.y) : "r"(a));
    return v;
}
__device__ __forceinline__ void sts16(uint32_t a, uint16_t v) {
    asm volatile("st.shared.u16 [%0], %1;" :: "r"(a), "h"(v) : "memory");
}

// ================= Kernel 1: Wh = h @ W via mma.sync (bf16-split-3) =================
#define WHI_OFF 0
#define WLO_OFF 32768
#define HB_OFF 65536
#define HBSZ 36864                 // 128 rows * 72 floats * 4
#define WS_OFF (HB_OFF + 2 * HBSZ) // 139264
#define AS_OFF (WS_OFF + 34816)    // 174080
#define DSM_WH (AS_OFF + 512 + 1024)

__global__ void __launch_bounds__(256) wh_kernel(const float* __restrict__ h,
                                                 const float* __restrict__ W,
                                                 const float* __restrict__ a) {
    extern __shared__ uint8_t dsm_raw[];
    const uint32_t sb0 = smem_u32(dsm_raw);
    const uint32_t sb = (sb0 + 1023u) & ~1023u;
    uint8_t* dsm = dsm_raw + (sb - sb0);

    const int tid = threadIdx.x, wid = tid >> 5, lid = tid & 31;
    const int row0 = blockIdx.x * 128;

    float* as_p = (float*)(dsm + AS_OFF);
    if (tid < 128) as_p[tid] = a[tid];

    const char* hsrc = (const char*)(h + (size_t)row0 * IND);

#define STAGEH(c)                                                              \
    do {                                                                       \
        const uint32_t hd = sb + HB_OFF + (uint32_t)(((c) & 1) * HBSZ);        \
        _Pragma("unroll")                                                      \
        for (int q = 0; q < 8; q++) {                                          \
            const int idx = tid + 256 * q;                                     \
            const int r = idx >> 4, ch = idx & 15;                             \
            cpa16(hd + (uint32_t)(r * 288 + ch * 16),                          \
                  hsrc + (size_t)r * 1024 + (c) * 256 + ch * 16);              \
        }                                                                      \
    } while (0)

    STAGEH(0);
    cpa_commit();

    // ---- W split staging: [n][k] bf16 hi/lo, chunk-xor swizzle ----
#pragma unroll 4
    for (int q = 0; q < 64; q++) {
        const int idx = tid + 256 * q;
        const int k = idx >> 6, n = idx & 63;
        const float val = __ldg(&W[idx]);
        const uint32_t hh = bf2(val, val) & 0xffffu;
        const float f = __uint_as_float(hh << 16);
        const uint32_t ll = bf2(val - f, val - f) & 0xffffu;
        const uint32_t off =
            (uint32_t)(n * 512 + (((k >> 3) ^ (n & 7)) << 4) + (k & 7) * 2);
        sts16(sb + WHI_OFF + off, (uint16_t)hh);
        sts16(sb + WLO_OFF + off, (uint16_t)ll);
    }

    const int wrow = wid;
    const int r0 = lid >> 2, c0l = (lid & 3) * 2;
    const int g = lid >> 3, rowin = lid & 7, khB = g & 1, nhf = g >> 1;
    const uint32_t abase = (uint32_t)(((wrow * 16 + r0) * 72 + c0l) * 4);
    uint32_t nbase[4], nxr[4];
#pragma unroll
    for (int nb = 0; nb < 4; nb++) {
        const int n = nb * 16 + nhf * 8 + rowin;
        nbase[nb] = (uint32_t)(n * 512);
        nxr[nb] = (uint32_t)(n & 7);
    }

    float4 acc[8];
#pragma unroll
    for (int nt = 0; nt < 8; nt++) acc[nt] = make_float4(0.f, 0.f, 0.f, 0.f);

    for (int c = 0; c < 4; c++) {
        cpa_wait0();
        __syncthreads();
        if (c < 3) {
            STAGEH(c + 1);
            cpa_commit();
        }
        const uint32_t hb = sb + HB_OFF + (uint32_t)((c & 1) * HBSZ);
#pragma unroll
        for (int ks = 0; ks < 4; ks++) {
            const uint32_t ab = hb + abase + (uint32_t)(ks * 64);
            const float2 q00 = lds_f2(ab);
            const float2 q01 = lds_f2(ab + 2304);
            const float2 q10 = lds_f2(ab + 32);
            const float2 q11 = lds_f2(ab + 2304 + 32);

            uint32_t ah[4], al[4];
            {
                const uint32_t h0 = bf2(q00.x, q00.y);
                const uint32_t h1 = bf2(q01.x, q01.y);
                const uint32_t h2 = bf2(q10.x, q10.y);
                const uint32_t h3 = bf2(q11.x, q11.y);
                ah[0] = h0; ah[1] = h1; ah[2] = h2; ah[3] = h3;
                al[0] = bf2(q00.x - __uint_as_float(h0 << 16),
                            q00.y - __uint_as_float(h0 & 0xffff0000u));
                al[1] = bf2(q01.x - __uint_as_float(h1 << 16),
                            q01.y - __uint_as_float(h1 & 0xffff0000u));
                al[2] = bf2(q10.x - __uint_as_float(h2 << 16),
                            q10.y - __uint_as_float(h2 & 0xffff0000u));
                al[3] = bf2(q11.x - __uint_as_float(h3 << 16),
                            q11.y - __uint_as_float(h3 & 0xffff0000u));
            }

            const uint32_t chx = (uint32_t)((c * 4 + ks) * 2 + khB);
#pragma unroll
            for (int nb = 0; nb < 4; nb++) {
                const uint32_t addr =
                    sb + WHI_OFF + nbase[nb] + ((chx ^ nxr[nb]) << 4);
                uint32_t bh0, bh1, bh2, bh3, bl0, bl1, bl2, bl3;
                ldmx4(bh0, bh1, bh2, bh3, addr);
                ldmx4(bl0, bl1, bl2, bl3, addr + 32768);
                float* d0 = (float*)&acc[2 * nb];
                float* d1 = (float*)&acc[2 * nb + 1];
                mma16816(d0, ah[0], ah[1], ah[2], ah[3], bh0, bh1);
                mma16816(d0, al[0], al[1], al[2], al[3], bh0, bh1);
                mma16816(d0, ah[0], ah[1], ah[2], ah[3], bl0, bl1);
                mma16816(d1, ah[0], ah[1], ah[2], ah[3], bh2, bh3);
                mma16816(d1, al[0], al[1], al[2], al[3], bh2, bh3);
                mma16816(d1, ah[0], ah[1], ah[2], ah[3], bl2, bl3);
            }
        }
    }
#undef STAGEH

    float* wsp = (float*)(dsm + WS_OFF);
#pragma unroll
    for (int nb = 0; nb < 4; nb++)
#pragma unroll
        for (int hf = 0; hf < 2; hf++) {
            const float4 v = acc[2 * nb + hf];
            const int col = nb * 16 + hf * 8 + c0l;
            const int rl = wrow * 16 + r0;
            *(float2*)&wsp[rl * 68 + col] = make_float2(v.x, v.y);
            *(float2*)&wsp[(rl + 8) * 68 + col] = make_float2(v.z, v.w);
        }
    __syncthreads();

    {
        const int row = wrow * 16 + (lid >> 1);
        const int cb = (lid & 1) * 32;
        float s1 = 0.f, s2 = 0.f;
#pragma unroll 8
        for (int cc = 0; cc < 32; cc++) {
            const float v = wsp[row * 68 + cb + cc];
            s1 = fmaf(v, as_p[cb + cc], s1);
            s2 = fmaf(v, as_p[64 + cb + cc], s2);
        }
        s1 += __shfl_xor_sync(0xffffffffu, s1, 1);
        s2 += __shfl_xor_sync(0xffffffffu, s2, 1);
        if ((lid & 1) == 0) {
            g_s1[row0 + row] = s1;
            g_s2[row0 + row] = s2;
        }
    }

    {
        const int d = tid & 63, rg = tid >> 6;
        uint32_t hi16[16], lo16[16];
#pragma unroll
        for (int p = 0; p < 16; p++) {
            const float p0 = wsp[(rg * 32 + 2 * p) * 68 + d];
            const float p1 = wsp[(rg * 32 + 2 * p + 1) * 68 + d];
            const uint32_t h2 = bf2(p0, p1);
            const float f0 = __uint_as_float(h2 << 16);
            const float f1 = __uint_as_float(h2 & 0xffff0000u);
            hi16[p] = h2;
            lo16[p] = bf2(p0 - f0, p1 - f1);
        }
        const size_t bb = (size_t)(row0 >> 11);
        const int j0l = (row0 & (NN - 1)) + rg * 32;
        char* dst = (char*)g_B + ((bb * DD + d) * NN + j0l) * 2;
#pragma unroll
        for (int qq = 0; qq < 4; qq++) {
            *(uint4*)(dst + qq * 16) = make_uint4(hi16[4 * qq], hi16[4 * qq + 1],
                                                  hi16[4 * qq + 2], hi16[4 * qq + 3]);
            *(uint4*)(dst + LOOFF + qq * 16) =
                make_uint4(lo16[4 * qq], lo16[4 * qq + 1], lo16[4 * qq + 2],
                           lo16[4 * qq + 3]);
        }
    }
}

// ================= Kernel 2: masked-softmax x Wh =================
// 256 threads, 64 rows/CTA, grid 256, 2 CTAs/SM. 8 warps = 4 row-blocks x 2 K-split.
// KTILE=32 (64 tiles). B-tile rows pad-80 (no swizzle), adj rows pad-144.
#define KT2 32
#define NT2 (NN / KT2)             // 64 tiles
#define BSTG2 10240                // 64 d-rows * 80 (hi) + same (lo @ +5120)
#define ASTG2 9216                 // 64 rows * 144
#define AOFF2 (4 * BSTG2)          // 40960
#define S2OFF2 (AOFF2 + 4 * ASTG2) // 77824
#define DSM_BYTES (S2OFF2 + 8192 + 1024)

__global__ void __launch_bounds__(256, 2) attn_kernel(const int* __restrict__ adj,
                                                      float* __restrict__ out) {
    extern __shared__ uint8_t dsm_raw[];
    uint32_t sb = smem_u32(dsm_raw);
    sb = (sb + 1023u) & ~1023u;

    const int tid = threadIdx.x, wid = tid >> 5, lid = tid & 31;
    const int wg = wid >> 2;        // K-split: 0 even tiles, 1 odd tiles
    const int wrow = wid & 3;       // 4 row-blocks of 16
    const int b = blockIdx.x >> 5;  // 32 CTAs per batch
    const int i0 = (blockIdx.x & 31) * 64;
    const int ibase = i0 + wrow * 16;
    const int r0 = lid >> 2, c0 = (lid & 3) * 2;

    const float s1_0 = g_s1[b * NN + ibase + r0];
    const float s1_1 = g_s1[b * NN + ibase + r0 + 8];
    float den0 = 0.f, den1 = 0.f;
    float4 acc[8];
#pragma unroll
    for (int nt = 0; nt < 8; nt++) acc[nt] = make_float4(0.f, 0.f, 0.f, 0.f);

    // B fragment addressing: pad-80 rows, no xor needed
    uint32_t nrel80[4], kh;
    {
        const int g = lid >> 3, rowin = lid & 7;
        kh = (uint32_t)((g & 1) * 16);
#pragma unroll
        for (int np = 0; np < 4; np++) {
            const int n = np * 16 + (g >> 1) * 8 + rowin;
            nrel80[np] = (uint32_t)(n * 80);
        }
    }

    // staging offsets
    const char* gbh = (const char*)g_B + (size_t)b * DD * NN * 2;
    const uint32_t bsw = (uint32_t)((tid >> 2) * 80 + (tid & 3) * 16);
    const uint32_t bgo = (uint32_t)((tid >> 2) * (NN * 2) + (tid & 3) * 16);
    const char* gadj = (const char*)(adj + ((size_t)b * NN + i0) * NN);

#define STAGE(t)                                                               \
    do {                                                                       \
        const uint32_t bd = sb + (((t) & 3) * BSTG2);                          \
        const size_t go = (size_t)(t) * (KT2 * 2);                             \
        cpa16(bd + bsw, gbh + bgo + go);                                       \
        cpa16(bd + bsw + 5120, gbh + bgo + go + LOOFF);                        \
        const uint32_t ad = sb + AOFF2 + (((t) & 3) * ASTG2);                  \
        const size_t jb = (size_t)(t) * (KT2 * 4);                             \
        _Pragma("unroll")                                                      \
        for (int q = 0; q < 2; q++) {                                          \
            const int idx = tid + 256 * q;                                     \
            const int rr_ = idx >> 3, ch_ = idx & 7;                           \
            cpa16(ad + rr_ * 144 + ch_ * 16,                                   \
                  gadj + (size_t)rr_ * (NN * 4) + jb + ch_ * 16);              \
        }                                                                      \
    } while (0)

    // s2 stage (8KB, once) + first two tiles
    cpa16(sb + S2OFF2 + tid * 16, (const char*)(g_s2 + b * NN) + tid * 16);
    cpa16(sb + S2OFF2 + (tid + 256) * 16,
          (const char*)(g_s2 + b * NN) + (tid + 256) * 16);
    STAGE(0);
    STAGE(1);
    cpa_commit();

    const uint32_t arow_base = (uint32_t)((wrow * 16 + r0) * 144);

    for (int i = 0; i < NT2 / 2; i++) {
        cpa_wait0();
        __syncthreads();
        if (i < NT2 / 2 - 1) {
            STAGE(2 * i + 2);
            STAGE(2 * i + 3);
            cpa_commit();
        }

        const int t = 2 * i + wg;
        const uint32_t bufb = sb + ((t & 3) * BSTG2);
        const uint32_t abuf = sb + AOFF2 + ((t & 3) * ASTG2) + arow_base;

#pragma unroll
        for (int ks = 0; ks < 2; ks++) {
            const uint32_t jcb = (uint32_t)((ks * 16 + c0) * 4);
            const int2 aj0 = lds_i2(abuf + jcb);
            const int2 aj1 = lds_i2(abuf + jcb + 32);
            const int2 aj2 = lds_i2(abuf + 8 * 144 + jcb);
            const int2 aj3 = lds_i2(abuf + 8 * 144 + jcb + 32);
            const uint32_t s2ad =
                sb + S2OFF2 + (uint32_t)((t * KT2 + ks * 16 + c0) * 4);
            const float2 s2a = lds_f2(s2ad);
            const float2 s2b = lds_f2(s2ad + 32);

            const float p0 = pe(s1_0 + s2a.x, aj0.x);
            const float p1 = pe(s1_0 + s2a.y, aj0.y);
            const float p2 = pe(s1_0 + s2b.x, aj1.x);
            const float p3 = pe(s1_0 + s2b.y, aj1.y);
            const float p4 = pe(s1_1 + s2a.x, aj2.x);
            const float p5 = pe(s1_1 + s2a.y, aj2.y);
            const float p6 = pe(s1_1 + s2b.x, aj3.x);
            const float p7 = pe(s1_1 + s2b.y, aj3.y);
            den0 += (p0 + p1) + (p2 + p3);
            den1 += (p4 + p5) + (p6 + p7);

            uint32_t ah[4], al[4];
            {
                const uint32_t h0 = bf2(p0, p1), h1 = bf2(p4, p5);
                const uint32_t h2 = bf2(p2, p3), h3 = bf2(p6, p7);
                ah[0] = h0; ah[1] = h1; ah[2] = h2; ah[3] = h3;
                al[0] = bf2(p0 - __uint_as_float(h0 << 16),
                            p1 - __uint_as_float(h0 & 0xffff0000u));
                al[1] = bf2(p4 - __uint_as_float(h1 << 16),
                            p5 - __uint_as_float(h1 & 0xffff0000u));
                al[2] = bf2(p2 - __uint_as_float(h2 << 16),
                            p3 - __uint_as_float(h2 & 0xffff0000u));
                al[3] = bf2(p6 - __uint_as_float(h3 << 16),
                            p7 - __uint_as_float(h3 & 0xffff0000u));
            }

            const uint32_t koff = (uint32_t)(ks * 32) + kh;
#pragma unroll
            for (int np = 0; np < 4; np++) {
                const uint32_t addr = bufb + nrel80[np] + koff;
                uint32_t h0, h1, h2, h3, l0, l1, l2, l3;
                ldmx4(h0, h1, h2, h3, addr);
                ldmx4(l0, l1, l2, l3, addr + 5120);
                float* d0 = (float*)&acc[2 * np];
                float* d1 = (float*)&acc[2 * np + 1];
                mma16816(d0, ah[0], ah[1], ah[2], ah[3], h0, h1);
                mma16816(d0, al[0], al[1], al[2], al[3], h0, h1);
                mma16816(d0, ah[0], ah[1], ah[2], ah[3], l0, l1);
                mma16816(d1, ah[0], ah[1], ah[2], ah[3], h2, h3);
                mma16816(d1, al[0], al[1], al[2], al[3], h2, h3);
                mma16816(d1, ah[0], ah[1], ah[2], ah[3], l2, l3);
            }
        }
    }
#undef STAGE

    __syncthreads();   // all reads of ring bufs done before reduction overwrites

    {
        float* redp = (float*)(dsm_raw + (sb - smem_u32(dsm_raw)));
        float* slot = redp + (size_t)(wrow * 32 + lid) * 36;
        if (wg == 1) {
#pragma unroll
            for (int nt = 0; nt < 8; nt++) *(float4*)(slot + nt * 4) = acc[nt];
            slot[32] = den0;
            slot[33] = den1;
        }
        __syncthreads();
        if (wg == 0) {
#pragma unroll
            for (int nt = 0; nt < 8; nt++) {
                const float4 v = *(const float4*)(slot + nt * 4);
                acc[nt].x += v.x; acc[nt].y += v.y;
                acc[nt].z += v.z; acc[nt].w += v.w;
            }
            den0 += slot[32];
            den1 += slot[33];

            den0 += __shfl_xor_sync(0xffffffffu, den0, 1);
            den0 += __shfl_xor_sync(0xffffffffu, den0, 2);
            den1 += __shfl_xor_sync(0xffffffffu, den1, 1);
            den1 += __shfl_xor_sync(0xffffffffu, den1, 2);
            const float inv0 = 1.0f / den0;
            const float inv1 = 1.0f / den1;

            float* o0 = out + (size_t)(b * NN + ibase + r0) * DD;
            float* o1 = o0 + (size_t)8 * DD;
#pragma unroll
            for (int nt = 0; nt < 8; nt++) {
                *(float2*)(o0 + nt * 8 + c0) =
                    make_float2(acc[nt].x * inv0, acc[nt].y * inv0);
                *(float2*)(o1 + nt * 8 + c0) =
                    make_float2(acc[nt].z * inv1, acc[nt].w * inv1);
            }
        }
    }
}

extern "C" void kernel_launch(void* const* d_in, const int* in_sizes, int n_in,
                              void* d_out, int out_size) {
    const float* h = nullptr;
    const int* adj = nullptr;
    const float* W = nullptr;
    const float* a = nullptr;
    for (int i = 0; i < n_in; i++) {
        const long long s = in_sizes[i];
        if (s == (long long)BB * NN * IND)      h   = (const float*)d_in[i];
        else if (s == (long long)BB * NN * NN)  adj = (const int*)d_in[i];
        else if (s == (long long)IND * DD)      W   = (const float*)d_in[i];
        else if (s == 2 * DD)                   a   = (const float*)d_in[i];
    }
    float* out = (float*)d_out;

    static bool attr_set = false;
    if (!attr_set) {
        cudaFuncSetAttribute(attn_kernel, cudaFuncAttributeMaxDynamicSharedMemorySize,
                             DSM_BYTES);
        cudaFuncSetAttribute(wh_kernel, cudaFuncAttributeMaxDynamicSharedMemorySize,
                             DSM_WH);
        attr_set = true;
    }

    wh_kernel<<<(BB * NN) / 128, 256, DSM_WH>>>(h, W, a);
    attn_kernel<<<BB * (NN / 64), 256, DSM_BYTES>>>(adj, out);
}

// round 14
// speedup vs baseline: 1.1778x; 1.1778x over previous
#include <cuda_runtime.h>
#include <cuda_bf16.h>
#include <cstdint>
#include <cstddef>

#define BB 8
#define NN 2048
#define IND 256
#define DD 64
#define ALPHA 0.2f
#define KTILE 64
#define NKT (NN / KTILE)   // 32

// ---------------- device scratch (allocation-free) ----------------
__device__ float g_s1[BB * NN];
__device__ float g_s2[BB * NN];
// hi half at [0, BB*DD*NN), lo half at +BB*DD*NN elements. layout [b][d][j]
__device__ __nv_bfloat16 g_B[(size_t)2 * BB * DD * NN];
#define LOOFF ((size_t)BB * DD * NN * 2)   // byte offset hi -> lo
// Pre-split W smem-image: hi at [0,32768), lo at [32768,65536)
__device__ uint8_t g_Wimg[65536];

// ---------------- helpers ----------------
__device__ __forceinline__ uint32_t smem_u32(const void* p) {
    uint32_t a;
    asm("{ .reg .u64 t; cvta.to.shared.u64 t, %1; cvt.u32.u64 %0, t; }"
        : "=r"(a) : "l"(p));
    return a;
}
// pack (first, second) -> bf16x2 with first in LOW half
__device__ __forceinline__ uint32_t bf2(float first, float second) {
    uint32_t r;
    asm("cvt.rn.bf16x2.f32 %0, %1, %2;" : "=r"(r) : "f"(second), "f"(first));
    return r;
}
__device__ __forceinline__ uint32_t sw128(uint32_t off) {
    return off ^ ((off >> 3) & 0x70);
}
__device__ __forceinline__ void ldmx4(uint32_t& r0, uint32_t& r1, uint32_t& r2,
                                      uint32_t& r3, uint32_t addr) {
    asm volatile("ldmatrix.sync.aligned.m8n8.x4.shared.b16 {%0,%1,%2,%3}, [%4];"
                 : "=r"(r0), "=r"(r1), "=r"(r2), "=r"(r3) : "r"(addr));
}
__device__ __forceinline__ void mma16816(float* d, uint32_t a0, uint32_t a1,
                                         uint32_t a2, uint32_t a3, uint32_t b0,
                                         uint32_t b1) {
    asm volatile(
        "mma.sync.aligned.m16n8k16.row.col.f32.bf16.bf16.f32 "
        "{%0,%1,%2,%3}, {%4,%5,%6,%7}, {%8,%9}, {%0,%1,%2,%3};"
        : "+f"(d[0]), "+f"(d[1]), "+f"(d[2]), "+f"(d[3])
        : "r"(a0), "r"(a1), "r"(a2), "r"(a3), "r"(b0), "r"(b1));
}
__device__ __forceinline__ float pe(float e, int m) {
    e = fmaxf(e, ALPHA * e);
    return m ? __expf(e) : 0.f;
}
__device__ __forceinline__ void cpa16(uint32_t dst, const void* src) {
    asm volatile("cp.async.cg.shared.global [%0], [%1], 16;"
                 :: "r"(dst), "l"(src) : "memory");
}
__device__ __forceinline__ void cpa_commit() {
    asm volatile("cp.async.commit_group;" ::: "memory");
}
__device__ __forceinline__ void cpa_wait0() {
    asm volatile("cp.async.wait_group 0;" ::: "memory");
}
__device__ __forceinline__ int2 lds_i2(uint32_t a) {
    int2 v;
    asm volatile("ld.shared.v2.b32 {%0,%1}, [%2];" : "=r"(v.x), "=r"(v.y) : "r"(a));
    return v;
}
__device__ __forceinline__ float2 lds_f2(uint32_t a) {
    float2 v;
    asm volatile("ld.shared.v2.f32 {%0,%1}, [%2];" : "=f"(v.x), "=f"(v.y) : "r"(a));
    return v;
}

// ================= Kernel 0: build W hi/lo smem-image once =================
// image layout: off = n*512 + (((k>>3)^(n&7))<<4) + (k&7)*2 ; lo at +32768.
// 8 CTAs x 256 thr: thread -> one 16B hi chunk + matching lo chunk (coalesced STG).
__global__ void __launch_bounds__(256) wprep_kernel(const float* __restrict__ W) {
    const int g = blockIdx.x * 256 + threadIdx.x;   // 0..2047 chunk id
    const int n = g >> 5, c = g & 31;
    const int kb = ((c ^ (n & 7)) << 3);
    uint32_t hi4[4], lo4[4];
#pragma unroll
    for (int p = 0; p < 4; p++) {
        const float v0 = __ldg(&W[(kb + 2 * p) * DD + n]);
        const float v1 = __ldg(&W[(kb + 2 * p + 1) * DD + n]);
        const uint32_t h2 = bf2(v0, v1);
        const float f0 = __uint_as_float(h2 << 16);
        const float f1 = __uint_as_float(h2 & 0xffff0000u);
        hi4[p] = h2;
        lo4[p] = bf2(v0 - f0, v1 - f1);
    }
    *(uint4*)(g_Wimg + g * 16) = make_uint4(hi4[0], hi4[1], hi4[2], hi4[3]);
    *(uint4*)(g_Wimg + 32768 + g * 16) = make_uint4(lo4[0], lo4[1], lo4[2], lo4[3]);
}

// ================= Kernel 1: Wh = h @ W via mma.sync (bf16-split-3) =================
#define WHI_OFF 0
#define HB_OFF 65536
#define HBSZ 36864                 // 128 rows * 72 floats * 4
#define WS_OFF (HB_OFF + 2 * HBSZ) // 139264
#define AS_OFF (WS_OFF + 34816)    // 174080
#define DSM_WH (AS_OFF + 512 + 1024)

__global__ void __launch_bounds__(256) wh_kernel(const float* __restrict__ h,
                                                 const float* __restrict__ a) {
    extern __shared__ uint8_t dsm_raw[];
    const uint32_t sb0 = smem_u32(dsm_raw);
    const uint32_t sb = (sb0 + 1023u) & ~1023u;
    uint8_t* dsm = dsm_raw + (sb - sb0);

    const int tid = threadIdx.x, wid = tid >> 5, lid = tid & 31;
    const int row0 = blockIdx.x * 128;

    float* as_p = (float*)(dsm + AS_OFF);
    if (tid < 128) as_p[tid] = a[tid];

    const char* hsrc = (const char*)(h + (size_t)row0 * IND);

#define STAGEH(c)                                                              \
    do {                                                                       \
        const uint32_t hd = sb + HB_OFF + (uint32_t)(((c) & 1) * HBSZ);        \
        _Pragma("unroll")                                                      \
        for (int q = 0; q < 8; q++) {                                          \
            const int idx = tid + 256 * q;                                     \
            const int r = idx >> 4, ch = idx & 15;                             \
            cpa16(hd + (uint32_t)(r * 288 + ch * 16),                          \
                  hsrc + (size_t)r * 1024 + (c) * 256 + ch * 16);              \
        }                                                                      \
    } while (0)

    // W image (64KB) + first h chunk in one group
#pragma unroll
    for (int q = 0; q < 16; q++) {
        const int idx = tid + 256 * q;
        cpa16(sb + WHI_OFF + (uint32_t)(idx * 16), g_Wimg + idx * 16);
    }
    STAGEH(0);
    cpa_commit();

    const int wrow = wid;
    const int r0 = lid >> 2, c0l = (lid & 3) * 2;
    const int g = lid >> 3, rowin = lid & 7, khB = g & 1, nhf = g >> 1;
    const uint32_t abase = (uint32_t)(((wrow * 16 + r0) * 72 + c0l) * 4);
    uint32_t nbase[4], nxr[4];
#pragma unroll
    for (int nb = 0; nb < 4; nb++) {
        const int n = nb * 16 + nhf * 8 + rowin;
        nbase[nb] = (uint32_t)(n * 512);
        nxr[nb] = (uint32_t)(n & 7);
    }

    float4 acc[8];
#pragma unroll
    for (int nt = 0; nt < 8; nt++) acc[nt] = make_float4(0.f, 0.f, 0.f, 0.f);

    for (int c = 0; c < 4; c++) {
        cpa_wait0();
        __syncthreads();
        if (c < 3) {
            STAGEH(c + 1);
            cpa_commit();
        }
        const uint32_t hb = sb + HB_OFF + (uint32_t)((c & 1) * HBSZ);
#pragma unroll
        for (int ks = 0; ks < 4; ks++) {
            const uint32_t ab = hb + abase + (uint32_t)(ks * 64);
            const float2 q00 = lds_f2(ab);
            const float2 q01 = lds_f2(ab + 2304);
            const float2 q10 = lds_f2(ab + 32);
            const float2 q11 = lds_f2(ab + 2304 + 32);

            uint32_t ah[4], al[4];
            {
                const uint32_t h0 = bf2(q00.x, q00.y);
                const uint32_t h1 = bf2(q01.x, q01.y);
                const uint32_t h2 = bf2(q10.x, q10.y);
                const uint32_t h3 = bf2(q11.x, q11.y);
                ah[0] = h0; ah[1] = h1; ah[2] = h2; ah[3] = h3;
                al[0] = bf2(q00.x - __uint_as_float(h0 << 16),
                            q00.y - __uint_as_float(h0 & 0xffff0000u));
                al[1] = bf2(q01.x - __uint_as_float(h1 << 16),
                            q01.y - __uint_as_float(h1 & 0xffff0000u));
                al[2] = bf2(q10.x - __uint_as_float(h2 << 16),
                            q10.y - __uint_as_float(h2 & 0xffff0000u));
                al[3] = bf2(q11.x - __uint_as_float(h3 << 16),
                            q11.y - __uint_as_float(h3 & 0xffff0000u));
            }

            const uint32_t chx = (uint32_t)((c * 4 + ks) * 2 + khB);
#pragma unroll
            for (int nb = 0; nb < 4; nb++) {
                const uint32_t addr =
                    sb + WHI_OFF + nbase[nb] + ((chx ^ nxr[nb]) << 4);
                uint32_t bh0, bh1, bh2, bh3, bl0, bl1, bl2, bl3;
                ldmx4(bh0, bh1, bh2, bh3, addr);
                ldmx4(bl0, bl1, bl2, bl3, addr + 32768);
                float* d0 = (float*)&acc[2 * nb];
                float* d1 = (float*)&acc[2 * nb + 1];
                mma16816(d0, ah[0], ah[1], ah[2], ah[3], bh0, bh1);
                mma16816(d0, al[0], al[1], al[2], al[3], bh0, bh1);
                mma16816(d0, ah[0], ah[1], ah[2], ah[3], bl0, bl1);
                mma16816(d1, ah[0], ah[1], ah[2], ah[3], bh2, bh3);
                mma16816(d1, al[0], al[1], al[2], al[3], bh2, bh3);
                mma16816(d1, ah[0], ah[1], ah[2], ah[3], bl2, bl3);
            }
        }
    }
#undef STAGEH

    float* wsp = (float*)(dsm + WS_OFF);
#pragma unroll
    for (int nb = 0; nb < 4; nb++)
#pragma unroll
        for (int hf = 0; hf < 2; hf++) {
            const float4 v = acc[2 * nb + hf];
            const int col = nb * 16 + hf * 8 + c0l;
            const int rl = wrow * 16 + r0;
            *(float2*)&wsp[rl * 68 + col] = make_float2(v.x, v.y);
            *(float2*)&wsp[(rl + 8) * 68 + col] = make_float2(v.z, v.w);
        }
    __syncthreads();

    {
        const int row = wrow * 16 + (lid >> 1);
        const int cb = (lid & 1) * 32;
        float s1 = 0.f, s2 = 0.f;
#pragma unroll 8
        for (int cc = 0; cc < 32; cc++) {
            const float v = wsp[row * 68 + cb + cc];
            s1 = fmaf(v, as_p[cb + cc], s1);
            s2 = fmaf(v, as_p[64 + cb + cc], s2);
        }
        s1 += __shfl_xor_sync(0xffffffffu, s1, 1);
        s2 += __shfl_xor_sync(0xffffffffu, s2, 1);
        if ((lid & 1) == 0) {
            g_s1[row0 + row] = s1;
            g_s2[row0 + row] = s2;
        }
    }

    {
        const int d = tid & 63, rg = tid >> 6;
        uint32_t hi16[16], lo16[16];
#pragma unroll
        for (int p = 0; p < 16; p++) {
            const float p0 = wsp[(rg * 32 + 2 * p) * 68 + d];
            const float p1 = wsp[(rg * 32 + 2 * p + 1) * 68 + d];
            const uint32_t h2 = bf2(p0, p1);
            const float f0 = __uint_as_float(h2 << 16);
            const float f1 = __uint_as_float(h2 & 0xffff0000u);
            hi16[p] = h2;
            lo16[p] = bf2(p0 - f0, p1 - f1);
        }
        const size_t bb = (size_t)(row0 >> 11);
        const int j0l = (row0 & (NN - 1)) + rg * 32;
        char* dst = (char*)g_B + ((bb * DD + d) * NN + j0l) * 2;
#pragma unroll
        for (int qq = 0; qq < 4; qq++) {
            *(uint4*)(dst + qq * 16) = make_uint4(hi16[4 * qq], hi16[4 * qq + 1],
                                                  hi16[4 * qq + 2], hi16[4 * qq + 3]);
            *(uint4*)(dst + LOOFF + qq * 16) =
                make_uint4(lo16[4 * qq], lo16[4 * qq + 1], lo16[4 * qq + 2],
                           lo16[4 * qq + 3]);
        }
    }
}

// ================= Kernel 2: masked-softmax x Wh (R11-proven config) =================
// 512 threads, 128 rows/CTA, grid 128. 16 warps = 8 row-blocks x 2 K-split.
#define BSTG 16384
#define ASTG 34816                 // 128 rows * 272 B
#define AOFF (4 * BSTG)            // 65536
#define S2OFF (AOFF + 4 * ASTG)    // 204800
#define DSM_BYTES (S2OFF + 8192 + 1024)

__global__ void __launch_bounds__(512, 1) attn_kernel(const int* __restrict__ adj,
                                                      float* __restrict__ out) {
    extern __shared__ uint8_t dsm_raw[];
    uint32_t sb = smem_u32(dsm_raw);
    sb = (sb + 1023u) & ~1023u;

    const int tid = threadIdx.x, wid = tid >> 5, lid = tid & 31;
    const int wg = wid >> 3;
    const int wrow = wid & 7;
    const int b = blockIdx.x >> 4;
    const int i0 = (blockIdx.x & 15) * 128;
    const int ibase = i0 + wrow * 16;
    const int r0 = lid >> 2, c0 = (lid & 3) * 2;

    const float s1_0 = g_s1[b * NN + ibase + r0];
    const float s1_1 = g_s1[b * NN + ibase + r0 + 8];
    float den0 = 0.f, den1 = 0.f;
    float4 acc[8];
#pragma unroll
    for (int nt = 0; nt < 8; nt++) acc[nt] = make_float4(0.f, 0.f, 0.f, 0.f);

    uint32_t nrel[4], nxor[4], kh;
    {
        const int g = lid >> 3, rowin = lid & 7;
        kh = (uint32_t)((g & 1) * 16);
#pragma unroll
        for (int np = 0; np < 4; np++) {
            const int n = np * 16 + (g >> 1) * 8 + rowin;
            nrel[np] = (uint32_t)(n * 128);
            nxor[np] = (uint32_t)((n & 7) << 4);
        }
    }

    const char* gbh = (const char*)g_B + (size_t)b * DD * NN * 2;
    const uint32_t ssw0 = sw128((uint32_t)((tid >> 3) * 128 + (tid & 7) * 16));
    const uint32_t sgo0 = (uint32_t)((tid >> 3) * NN * 2 + (tid & 7) * 16);

    const char* gadj = (const char*)(adj + ((size_t)b * NN + i0) * NN);

#define STAGE(t)                                                               \
    do {                                                                       \
        const uint32_t bd = sb + (((t) & 3) * BSTG);                           \
        const size_t go = (size_t)(t) * (KTILE * 2);                           \
        cpa16(bd + ssw0, gbh + sgo0 + go);                                     \
        cpa16(bd + ssw0 + 8192, gbh + sgo0 + go + LOOFF);                      \
        const uint32_t ad = sb + AOFF + (((t) & 3) * ASTG);                    \
        const size_t jb = (size_t)(t) * (KTILE * 4);                           \
        _Pragma("unroll")                                                      \
        for (int q = 0; q < 4; q++) {                                          \
            const int idx = tid + 512 * q;                                     \
            const int rr_ = idx >> 4, ch_ = idx & 15;                          \
            cpa16(ad + rr_ * 272 + ch_ * 16,                                   \
                  gadj + (size_t)rr_ * (NN * 4) + jb + ch_ * 16);              \
        }                                                                      \
    } while (0)

    cpa16(sb + S2OFF + tid * 16, (const char*)(g_s2 + b * NN) + tid * 16);
    STAGE(0);
    STAGE(1);
    cpa_commit();

    const uint32_t arow_base = (uint32_t)((wrow * 16 + r0) * 272);

    for (int i = 0; i < NKT / 2; i++) {
        cpa_wait0();
        __syncthreads();
        if (i < NKT / 2 - 1) {
            STAGE(2 * i + 2);
            STAGE(2 * i + 3);
            cpa_commit();
        }

        const int t = 2 * i + wg;
        const uint32_t bufb = sb + ((t & 3) * BSTG);
        const uint32_t abuf = sb + AOFF + ((t & 3) * ASTG) + arow_base;

#pragma unroll
        for (int ks = 0; ks < 4; ks++) {
            const uint32_t jcb = (uint32_t)((ks * 16 + c0) * 4);
            const int2 aj0 = lds_i2(abuf + jcb);
            const int2 aj1 = lds_i2(abuf + jcb + 32);
            const int2 aj2 = lds_i2(abuf + 8 * 272 + jcb);
            const int2 aj3 = lds_i2(abuf + 8 * 272 + jcb + 32);
            const uint32_t s2ad = sb + S2OFF + (uint32_t)((t * 64 + ks * 16 + c0) * 4);
            const float2 s2a = lds_f2(s2ad);
            const float2 s2b = lds_f2(s2ad + 32);

            const float p0 = pe(s1_0 + s2a.x, aj0.x);
            const float p1 = pe(s1_0 + s2a.y, aj0.y);
            const float p2 = pe(s1_0 + s2b.x, aj1.x);
            const float p3 = pe(s1_0 + s2b.y, aj1.y);
            const float p4 = pe(s1_1 + s2a.x, aj2.x);
            const float p5 = pe(s1_1 + s2a.y, aj2.y);
            const float p6 = pe(s1_1 + s2b.x, aj3.x);
            const float p7 = pe(s1_1 + s2b.y, aj3.y);
            den0 += (p0 + p1) + (p2 + p3);
            den1 += (p4 + p5) + (p6 + p7);

            uint32_t ah[4], al[4];
            {
                const uint32_t h0 = bf2(p0, p1), h1 = bf2(p4, p5);
                const uint32_t h2 = bf2(p2, p3), h3 = bf2(p6, p7);
                ah[0] = h0; ah[1] = h1; ah[2] = h2; ah[3] = h3;
                al[0] = bf2(p0 - __uint_as_float(h0 << 16),
                            p1 - __uint_as_float(h0 & 0xffff0000u));
                al[1] = bf2(p4 - __uint_as_float(h1 << 16),
                            p5 - __uint_as_float(h1 & 0xffff0000u));
                al[2] = bf2(p2 - __uint_as_float(h2 << 16),
                            p3 - __uint_as_float(h2 & 0xffff0000u));
                al[3] = bf2(p6 - __uint_as_float(h3 << 16),
                            p7 - __uint_as_float(h3 & 0xffff0000u));
            }

#pragma unroll
            for (int np = 0; np < 4; np++) {
                const uint32_t off = ((uint32_t)(ks * 32) + kh) ^ nxor[np];
                const uint32_t addr = bufb + nrel[np] + off;
                uint32_t h0, h1, h2, h3, l0, l1, l2, l3;
                ldmx4(h0, h1, h2, h3, addr);
                ldmx4(l0, l1, l2, l3, addr + 8192);
                float* d0 = (float*)&acc[2 * np];
                float* d1 = (float*)&acc[2 * np + 1];
                mma16816(d0, ah[0], ah[1], ah[2], ah[3], h0, h1);
                mma16816(d0, al[0], al[1], al[2], al[3], h0, h1);
                mma16816(d0, ah[0], ah[1], ah[2], ah[3], l0, l1);
                mma16816(d1, ah[0], ah[1], ah[2], ah[3], h2, h3);
                mma16816(d1, al[0], al[1], al[2], al[3], h2, h3);
                mma16816(d1, ah[0], ah[1], ah[2], ah[3], l2, l3);
            }
        }
    }
#undef STAGE

    __syncthreads();

    {
        float* redp = (float*)(dsm_raw + (sb - smem_u32(dsm_raw)));
        float* slot = redp + (size_t)(wrow * 32 + lid) * 36;
        if (wg == 1) {
#pragma unroll
            for (int nt = 0; nt < 8; nt++) *(float4*)(slot + nt * 4) = acc[nt];
            slot[32] = den0;
            slot[33] = den1;
        }
        __syncthreads();
        if (wg == 0) {
#pragma unroll
            for (int nt = 0; nt < 8; nt++) {
                const float4 v = *(const float4*)(slot + nt * 4);
                acc[nt].x += v.x; acc[nt].y += v.y;
                acc[nt].z += v.z; acc[nt].w += v.w;
            }
            den0 += slot[32];
            den1 += slot[33];

            den0 += __shfl_xor_sync(0xffffffffu, den0, 1);
            den0 += __shfl_xor_sync(0xffffffffu, den0, 2);
            den1 += __shfl_xor_sync(0xffffffffu, den1, 1);
            den1 += __shfl_xor_sync(0xffffffffu, den1, 2);
            const float inv0 = 1.0f / den0;
            const float inv1 = 1.0f / den1;

            float* o0 = out + (size_t)(b * NN + ibase + r0) * DD;
            float* o1 = o0 + (size_t)8 * DD;
#pragma unroll
            for (int nt = 0; nt < 8; nt++) {
                *(float2*)(o0 + nt * 8 + c0) =
                    make_float2(acc[nt].x * inv0, acc[nt].y * inv0);
                *(float2*)(o1 + nt * 8 + c0) =
                    make_float2(acc[nt].z * inv1, acc[nt].w * inv1);
            }
        }
    }
}

extern "C" void kernel_launch(void* const* d_in, const int* in_sizes, int n_in,
                              void* d_out, int out_size) {
    const float* h = nullptr;
    const int* adj = nullptr;
    const float* W = nullptr;
    const float* a = nullptr;
    for (int i = 0; i < n_in; i++) {
        const long long s = in_sizes[i];
        if (s == (long long)BB * NN * IND)      h   = (const float*)d_in[i];
        else if (s == (long long)BB * NN * NN)  adj = (const int*)d_in[i];
        else if (s == (long long)IND * DD)      W   = (const float*)d_in[i];
        else if (s == 2 * DD)                   a   = (const float*)d_in[i];
    }
    float* out = (float*)d_out;

    static bool attr_set = false;
    if (!attr_set) {
        cudaFuncSetAttribute(attn_kernel, cudaFuncAttributeMaxDynamicSharedMemorySize,
                             DSM_BYTES);
        cudaFuncSetAttribute(wh_kernel, cudaFuncAttributeMaxDynamicSharedMemorySize,
                             DSM_WH);
        attr_set = true;
    }

    wprep_kernel<<<8, 256>>>(W);
    wh_kernel<<<(BB * NN) / 128, 256, DSM_WH>>>(h, a);
    attn_kernel<<<BB * (NN / 128), 512, DSM_BYTES>>>(adj, out);
}

// round 16
// speedup vs baseline: 1.3226x; 1.1230x over previous
#include <cuda_runtime.h>
#include <cuda_bf16.h>
#include <cstdint>
#include <cstddef>

#define BB 8
#define NN 2048
#define IND 256
#define DD 64
#define ALPHA 0.2f
#define KTILE 64
#define NKT (NN / KTILE)   // 32
#define LOG2E 1.4426950408889634f

// ---------------- device scratch (allocation-free) ----------------
__device__ float g_s1[BB * NN];   // pre-scaled by LOG2E
__device__ float g_s2[BB * NN];   // pre-scaled by LOG2E
// hi half at [0, BB*DD*NN), lo half at +BB*DD*NN elements. layout [b][d][j]
__device__ __nv_bfloat16 g_B[(size_t)2 * BB * DD * NN];
#define LOOFF ((size_t)BB * DD * NN * 2)   // byte offset hi -> lo
// Pre-split W smem-image: hi at [0,32768), lo at [32768,65536)
__device__ uint8_t g_Wimg[65536];

// ---------------- helpers ----------------
__device__ __forceinline__ uint32_t smem_u32(const void* p) {
    uint32_t a;
    asm("{ .reg .u64 t; cvta.to.shared.u64 t, %1; cvt.u32.u64 %0, t; }"
        : "=r"(a) : "l"(p));
    return a;
}
// pack (first, second) -> bf16x2 with first in LOW half
__device__ __forceinline__ uint32_t bf2(float first, float second) {
    uint32_t r;
    asm("cvt.rn.bf16x2.f32 %0, %1, %2;" : "=r"(r) : "f"(second), "f"(first));
    return r;
}
__device__ __forceinline__ uint32_t sw128(uint32_t off) {
    return off ^ ((off >> 3) & 0x70);
}
__device__ __forceinline__ void ldmx4(uint32_t& r0, uint32_t& r1, uint32_t& r2,
                                      uint32_t& r3, uint32_t addr) {
    asm volatile("ldmatrix.sync.aligned.m8n8.x4.shared.b16 {%0,%1,%2,%3}, [%4];"
                 : "=r"(r0), "=r"(r1), "=r"(r2), "=r"(r3) : "r"(addr));
}
__device__ __forceinline__ void mma16816(float* d, uint32_t a0, uint32_t a1,
                                         uint32_t a2, uint32_t a3, uint32_t b0,
                                         uint32_t b1) {
    asm volatile(
        "mma.sync.aligned.m16n8k16.row.col.f32.bf16.bf16.f32 "
        "{%0,%1,%2,%3}, {%4,%5,%6,%7}, {%8,%9}, {%0,%1,%2,%3};"
        : "+f"(d[0]), "+f"(d[1]), "+f"(d[2]), "+f"(d[3])
        : "r"(a0), "r"(a1), "r"(a2), "r"(a3), "r"(b0), "r"(b1));
}
// inputs pre-scaled by LOG2E; lrelu commutes with positive scaling
__device__ __forceinline__ float pe(float e, int m) {
    e = fmaxf(e, ALPHA * e);
    float r;
    asm("ex2.approx.f32 %0, %1;" : "=f"(r) : "f"(e));
    return m ? r : 0.f;
}
__device__ __forceinline__ void cpa16(uint32_t dst, const void* src) {
    asm volatile("cp.async.cg.shared.global [%0], [%1], 16;"
                 :: "r"(dst), "l"(src) : "memory");
}
__device__ __forceinline__ void cpa_commit() {
    asm volatile("cp.async.commit_group;" ::: "memory");
}
__device__ __forceinline__ void cpa_wait0() {
    asm volatile("cp.async.wait_group 0;" ::: "memory");
}
__device__ __forceinline__ int2 lds_i2(uint32_t a) {
    int2 v;
    asm volatile("ld.shared.v2.b32 {%0,%1}, [%2];" : "=r"(v.x), "=r"(v.y) : "r"(a));
    return v;
}
__device__ __forceinline__ float2 lds_f2(uint32_t a) {
    float2 v;
    asm volatile("ld.shared.v2.f32 {%0,%1}, [%2];" : "=f"(v.x), "=f"(v.y) : "r"(a));
    return v;
}

// ================= Kernel 0: build W hi/lo smem-image (smem-transpose) =================
// For chunk (n, c): k-range = (c^(n&7))*8..+8 -> k>>3 has same high bits as c.
// CTA q owns c in [8q, 8q+8) -> needs only k in [64q, 64q+64): 16KB coalesced slice.
// NOTE: ws row pitch is 65 floats (conflict-free transposed reads) -> smem stores
// MUST be scalar; a float4 store at odd k would be 16B-misaligned (R15 trap).
__global__ void __launch_bounds__(256) wprep_kernel(const float* __restrict__ W) {
    __shared__ float ws[64 * 65];
    const int q = blockIdx.x;          // 0..3
    const int tid = threadIdx.x;

#pragma unroll
    for (int r = 0; r < 4; r++) {      // 1024 float4-sized chunks, coalesced LDG
        const int e = tid + 256 * r;
        const int k = e >> 4, ch4 = (e & 15) * 4;
        const float4 v = *(const float4*)&W[(q * 64 + k) * 64 + ch4];
        float* dstp = &ws[k * 65 + ch4];
        dstp[0] = v.x;
        dstp[1] = v.y;
        dstp[2] = v.z;
        dstp[3] = v.w;
    }
    __syncthreads();

#pragma unroll
    for (int u = 0; u < 2; u++) {
        const int e = tid * 2 + u;
        const int n = e >> 3, cl = e & 7;
        const int c = q * 8 + cl;
        const int kbl = (cl ^ (n & 7)) * 8;   // local k base
        uint32_t hi4[4], lo4[4];
#pragma unroll
        for (int p = 0; p < 4; p++) {
            const float v0 = ws[(kbl + 2 * p) * 65 + n];
            const float v1 = ws[(kbl + 2 * p + 1) * 65 + n];
            const uint32_t h2 = bf2(v0, v1);
            const float f0 = __uint_as_float(h2 << 16);
            const float f1 = __uint_as_float(h2 & 0xffff0000u);
            hi4[p] = h2;
            lo4[p] = bf2(v0 - f0, v1 - f1);
        }
        const int g = n * 32 + c;
        *(uint4*)(g_Wimg + g * 16) = make_uint4(hi4[0], hi4[1], hi4[2], hi4[3]);
        *(uint4*)(g_Wimg + 32768 + g * 16) =
            make_uint4(lo4[0], lo4[1], lo4[2], lo4[3]);
    }
}

// ================= Kernel 1: Wh = h @ W via mma.sync (bf16-split-3) =================
#define WHI_OFF 0
#define HB_OFF 65536
#define HBSZ 36864                 // 128 rows * 72 floats * 4
#define WS_OFF (HB_OFF + 2 * HBSZ) // 139264
#define AS_OFF (WS_OFF + 34816)    // 174080
#define DSM_WH (AS_OFF + 512 + 1024)

__global__ void __launch_bounds__(256) wh_kernel(const float* __restrict__ h,
                                                 const float* __restrict__ a) {
    extern __shared__ uint8_t dsm_raw[];
    const uint32_t sb0 = smem_u32(dsm_raw);
    const uint32_t sb = (sb0 + 1023u) & ~1023u;
    uint8_t* dsm = dsm_raw + (sb - sb0);

    const int tid = threadIdx.x, wid = tid >> 5, lid = tid & 31;
    const int row0 = blockIdx.x * 128;

    float* as_p = (float*)(dsm + AS_OFF);
    if (tid < 128) as_p[tid] = a[tid];

    const char* hsrc = (const char*)(h + (size_t)row0 * IND);

#define STAGEH(c)                                                              \
    do {                                                                       \
        const uint32_t hd = sb + HB_OFF + (uint32_t)(((c) & 1) * HBSZ);        \
        _Pragma("unroll")                                                      \
        for (int q = 0; q < 8; q++) {                                          \
            const int idx = tid + 256 * q;                                     \
            const int r = idx >> 4, ch = idx & 15;                             \
            cpa16(hd + (uint32_t)(r * 288 + ch * 16),                          \
                  hsrc + (size_t)r * 1024 + (c) * 256 + ch * 16);              \
        }                                                                      \
    } while (0)

    // W image (64KB) + first h chunk in one group
#pragma unroll
    for (int q = 0; q < 16; q++) {
        const int idx = tid + 256 * q;
        cpa16(sb + WHI_OFF + (uint32_t)(idx * 16), g_Wimg + idx * 16);
    }
    STAGEH(0);
    cpa_commit();

    const int wrow = wid;
    const int r0 = lid >> 2, c0l = (lid & 3) * 2;
    const int g = lid >> 3, rowin = lid & 7, khB = g & 1, nhf = g >> 1;
    const uint32_t abase = (uint32_t)(((wrow * 16 + r0) * 72 + c0l) * 4);
    uint32_t nbase[4], nxr[4];
#pragma unroll
    for (int nb = 0; nb < 4; nb++) {
        const int n = nb * 16 + nhf * 8 + rowin;
        nbase[nb] = (uint32_t)(n * 512);
        nxr[nb] = (uint32_t)(n & 7);
    }

    float4 acc[8];
#pragma unroll
    for (int nt = 0; nt < 8; nt++) acc[nt] = make_float4(0.f, 0.f, 0.f, 0.f);

    for (int c = 0; c < 4; c++) {
        cpa_wait0();
        __syncthreads();
        if (c < 3) {
            STAGEH(c + 1);
            cpa_commit();
        }
        const uint32_t hb = sb + HB_OFF + (uint32_t)((c & 1) * HBSZ);
#pragma unroll
        for (int ks = 0; ks < 4; ks++) {
            const uint32_t ab = hb + abase + (uint32_t)(ks * 64);
            const float2 q00 = lds_f2(ab);
            const float2 q01 = lds_f2(ab + 2304);
            const float2 q10 = lds_f2(ab + 32);
            const float2 q11 = lds_f2(ab + 2304 + 32);

            uint32_t ah[4], al[4];
            {
                const uint32_t h0 = bf2(q00.x, q00.y);
                const uint32_t h1 = bf2(q01.x, q01.y);
                const uint32_t h2 = bf2(q10.x, q10.y);
                const uint32_t h3 = bf2(q11.x, q11.y);
                ah[0] = h0; ah[1] = h1; ah[2] = h2; ah[3] = h3;
                al[0] = bf2(q00.x - __uint_as_float(h0 << 16),
                            q00.y - __uint_as_float(h0 & 0xffff0000u));
                al[1] = bf2(q01.x - __uint_as_float(h1 << 16),
                            q01.y - __uint_as_float(h1 & 0xffff0000u));
                al[2] = bf2(q10.x - __uint_as_float(h2 << 16),
                            q10.y - __uint_as_float(h2 & 0xffff0000u));
                al[3] = bf2(q11.x - __uint_as_float(h3 << 16),
                            q11.y - __uint_as_float(h3 & 0xffff0000u));
            }

            const uint32_t chx = (uint32_t)((c * 4 + ks) * 2 + khB);
#pragma unroll
            for (int nb = 0; nb < 4; nb++) {
                const uint32_t addr =
                    sb + WHI_OFF + nbase[nb] + ((chx ^ nxr[nb]) << 4);
                uint32_t bh0, bh1, bh2, bh3, bl0, bl1, bl2, bl3;
                ldmx4(bh0, bh1, bh2, bh3, addr);
                ldmx4(bl0, bl1, bl2, bl3, addr + 32768);
                float* d0 = (float*)&acc[2 * nb];
                float* d1 = (float*)&acc[2 * nb + 1];
                mma16816(d0, ah[0], ah[1], ah[2], ah[3], bh0, bh1);
                mma16816(d0, al[0], al[1], al[2], al[3], bh0, bh1);
                mma16816(d0, ah[0], ah[1], ah[2], ah[3], bl0, bl1);
                mma16816(d1, ah[0], ah[1], ah[2], ah[3], bh2, bh3);
                mma16816(d1, al[0], al[1], al[2], al[3], bh2, bh3);
                mma16816(d1, ah[0], ah[1], ah[2], ah[3], bl2, bl3);
            }
        }
    }
#undef STAGEH

    float* wsp = (float*)(dsm + WS_OFF);
#pragma unroll
    for (int nb = 0; nb < 4; nb++)
#pragma unroll
        for (int hf = 0; hf < 2; hf++) {
            const float4 v = acc[2 * nb + hf];
            const int col = nb * 16 + hf * 8 + c0l;
            const int rl = wrow * 16 + r0;
            *(float2*)&wsp[rl * 68 + col] = make_float2(v.x, v.y);
            *(float2*)&wsp[(rl + 8) * 68 + col] = make_float2(v.z, v.w);
        }
    __syncthreads();

    {
        const int row = wrow * 16 + (lid >> 1);
        const int cb = (lid & 1) * 32;
        float s1 = 0.f, s2 = 0.f;
#pragma unroll 8
        for (int cc = 0; cc < 32; cc++) {
            const float v = wsp[row * 68 + cb + cc];
            s1 = fmaf(v, as_p[cb + cc], s1);
            s2 = fmaf(v, as_p[64 + cb + cc], s2);
        }
        s1 += __shfl_xor_sync(0xffffffffu, s1, 1);
        s2 += __shfl_xor_sync(0xffffffffu, s2, 1);
        if ((lid & 1) == 0) {
            g_s1[row0 + row] = s1 * LOG2E;   // pre-scale for ex2-based exp
            g_s2[row0 + row] = s2 * LOG2E;
        }
    }

    {
        const int d = tid & 63, rg = tid >> 6;
        uint32_t hi16[16], lo16[16];
#pragma unroll
        for (int p = 0; p < 16; p++) {
            const float p0 = wsp[(rg * 32 + 2 * p) * 68 + d];
            const float p1 = wsp[(rg * 32 + 2 * p + 1) * 68 + d];
            const uint32_t h2 = bf2(p0, p1);
            const float f0 = __uint_as_float(h2 << 16);
            const float f1 = __uint_as_float(h2 & 0xffff0000u);
            hi16[p] = h2;
            lo16[p] = bf2(p0 - f0, p1 - f1);
        }
        const size_t bb = (size_t)(row0 >> 11);
        const int j0l = (row0 & (NN - 1)) + rg * 32;
        char* dst = (char*)g_B + ((bb * DD + d) * NN + j0l) * 2;
#pragma unroll
        for (int qq = 0; qq < 4; qq++) {
            *(uint4*)(dst + qq * 16) = make_uint4(hi16[4 * qq], hi16[4 * qq + 1],
                                                  hi16[4 * qq + 2], hi16[4 * qq + 3]);
            *(uint4*)(dst + LOOFF + qq * 16) =
                make_uint4(lo16[4 * qq], lo16[4 * qq + 1], lo16[4 * qq + 2],
                           lo16[4 * qq + 3]);
        }
    }
}

// ================= Kernel 2: masked-softmax x Wh (R11-proven config) =================
// 512 threads, 128 rows/CTA, grid 128. 16 warps = 8 row-blocks x 2 K-split.
#define BSTG 16384
#define ASTG 34816                 // 128 rows * 272 B
#define AOFF (4 * BSTG)            // 65536
#define S2OFF (AOFF + 4 * ASTG)    // 204800
#define DSM_BYTES (S2OFF + 8192 + 1024)

__global__ void __launch_bounds__(512, 1) attn_kernel(const int* __restrict__ adj,
                                                      float* __restrict__ out) {
    extern __shared__ uint8_t dsm_raw[];
    uint32_t sb = smem_u32(dsm_raw);
    sb = (sb + 1023u) & ~1023u;

    const int tid = threadIdx.x, wid = tid >> 5, lid = tid & 31;
    const int wg = wid >> 3;
    const int wrow = wid & 7;
    const int b = blockIdx.x >> 4;
    const int i0 = (blockIdx.x & 15) * 128;
    const int ibase = i0 + wrow * 16;
    const int r0 = lid >> 2, c0 = (lid & 3) * 2;

    const float s1_0 = g_s1[b * NN + ibase + r0];
    const float s1_1 = g_s1[b * NN + ibase + r0 + 8];
    float den0 = 0.f, den1 = 0.f;
    float4 acc[8];
#pragma unroll
    for (int nt = 0; nt < 8; nt++) acc[nt] = make_float4(0.f, 0.f, 0.f, 0.f);

    uint32_t nrel[4], nxor[4], kh;
    {
        const int g = lid >> 3, rowin = lid & 7;
        kh = (uint32_t)((g & 1) * 16);
#pragma unroll
        for (int np = 0; np < 4; np++) {
            const int n = np * 16 + (g >> 1) * 8 + rowin;
            nrel[np] = (uint32_t)(n * 128);
            nxor[np] = (uint32_t)((n & 7) << 4);
        }
    }

    const char* gbh = (const char*)g_B + (size_t)b * DD * NN * 2;
    const uint32_t ssw0 = sw128((uint32_t)((tid >> 3) * 128 + (tid & 7) * 16));
    const uint32_t sgo0 = (uint32_t)((tid >> 3) * NN * 2 + (tid & 7) * 16);

    const char* gadj = (const char*)(adj + ((size_t)b * NN + i0) * NN);

#define STAGE(t)                                                               \
    do {                                                                       \
        const uint32_t bd = sb + (((t) & 3) * BSTG);                           \
        const size_t go = (size_t)(t) * (KTILE * 2);                           \
        cpa16(bd + ssw0, gbh + sgo0 + go);                                     \
        cpa16(bd + ssw0 + 8192, gbh + sgo0 + go + LOOFF);                      \
        const uint32_t ad = sb + AOFF + (((t) & 3) * ASTG);                    \
        const size_t jb = (size_t)(t) * (KTILE * 4);                           \
        _Pragma("unroll")                                                      \
        for (int q = 0; q < 4; q++) {                                          \
            const int idx = tid + 512 * q;                                     \
            const int rr_ = idx >> 4, ch_ = idx & 15;                          \
            cpa16(ad + rr_ * 272 + ch_ * 16,                                   \
                  gadj + (size_t)rr_ * (NN * 4) + jb + ch_ * 16);              \
        }                                                                      \
    } while (0)

    cpa16(sb + S2OFF + tid * 16, (const char*)(g_s2 + b * NN) + tid * 16);
    STAGE(0);
    STAGE(1);
    cpa_commit();

    const uint32_t arow_base = (uint32_t)((wrow * 16 + r0) * 272);

    for (int i = 0; i < NKT / 2; i++) {
        cpa_wait0();
        __syncthreads();
        if (i < NKT / 2 - 1) {
            STAGE(2 * i + 2);
            STAGE(2 * i + 3);
            cpa_commit();
        }

        const int t = 2 * i + wg;
        const uint32_t bufb = sb + ((t & 3) * BSTG);
        const uint32_t abuf = sb + AOFF + ((t & 3) * ASTG) + arow_base;

#pragma unroll
        for (int ks = 0; ks < 4; ks++) {
            const uint32_t jcb = (uint32_t)((ks * 16 + c0) * 4);
            const int2 aj0 = lds_i2(abuf + jcb);
            const int2 aj1 = lds_i2(abuf + jcb + 32);
            const int2 aj2 = lds_i2(abuf + 8 * 272 + jcb);
            const int2 aj3 = lds_i2(abuf + 8 * 272 + jcb + 32);
            const uint32_t s2ad = sb + S2OFF + (uint32_t)((t * 64 + ks * 16 + c0) * 4);
            const float2 s2a = lds_f2(s2ad);
            const float2 s2b = lds_f2(s2ad + 32);

            const float p0 = pe(s1_0 + s2a.x, aj0.x);
            const float p1 = pe(s1_0 + s2a.y, aj0.y);
            const float p2 = pe(s1_0 + s2b.x, aj1.x);
            const float p3 = pe(s1_0 + s2b.y, aj1.y);
            const float p4 = pe(s1_1 + s2a.x, aj2.x);
            const float p5 = pe(s1_1 + s2a.y, aj2.y);
            const float p6 = pe(s1_1 + s2b.x, aj3.x);
            const float p7 = pe(s1_1 + s2b.y, aj3.y);
            den0 += (p0 + p1) + (p2 + p3);
            den1 += (p4 + p5) + (p6 + p7);

            uint32_t ah[4], al[4];
            {
                const uint32_t h0 = bf2(p0, p1), h1 = bf2(p4, p5);
                const uint32_t h2 = bf2(p2, p3), h3 = bf2(p6, p7);
                ah[0] = h0; ah[1] = h1; ah[2] = h2; ah[3] = h3;
                al[0] = bf2(p0 - __uint_as_float(h0 << 16),
                            p1 - __uint_as_float(h0 & 0xffff0000u));
                al[1] = bf2(p4 - __uint_as_float(h1 << 16),
                            p5 - __uint_as_float(h1 & 0xffff0000u));
                al[2] = bf2(p2 - __uint_as_float(h2 << 16),
                            p3 - __uint_as_float(h2 & 0xffff0000u));
                al[3] = bf2(p6 - __uint_as_float(h3 << 16),
                            p7 - __uint_as_float(h3 & 0xffff0000u));
            }

#pragma unroll
            for (int np = 0; np < 4; np++) {
                const uint32_t off = ((uint32_t)(ks * 32) + kh) ^ nxor[np];
                const uint32_t addr = bufb + nrel[np] + off;
                uint32_t h0, h1, h2, h3, l0, l1, l2, l3;
                ldmx4(h0, h1, h2, h3, addr);
                ldmx4(l0, l1, l2, l3, addr + 8192);
                float* d0 = (float*)&acc[2 * np];
                float* d1 = (float*)&acc[2 * np + 1];
                mma16816(d0, ah[0], ah[1], ah[2], ah[3], h0, h1);
                mma16816(d0, al[0], al[1], al[2], al[3], h0, h1);
                mma16816(d0, ah[0], ah[1], ah[2], ah[3], l0, l1);
                mma16816(d1, ah[0], ah[1], ah[2], ah[3], h2, h3);
                mma16816(d1, al[0], al[1], al[2], al[3], h2, h3);
                mma16816(d1, ah[0], ah[1], ah[2], ah[3], l2, l3);
            }
        }
    }
#undef STAGE

    __syncthreads();

    {
        float* redp = (float*)(dsm_raw + (sb - smem_u32(dsm_raw)));
        float* slot = redp + (size_t)(wrow * 32 + lid) * 36;
        if (wg == 1) {
#pragma unroll
            for (int nt = 0; nt < 8; nt++) *(float4*)(slot + nt * 4) = acc[nt];
            slot[32] = den0;
            slot[33] = den1;
        }
        __syncthreads();
        if (wg == 0) {
#pragma unroll
            for (int nt = 0; nt < 8; nt++) {
                const float4 v = *(const float4*)(slot + nt * 4);
                acc[nt].x += v.x; acc[nt].y += v.y;
                acc[nt].z += v.z; acc[nt].w += v.w;
            }
            den0 += slot[32];
            den1 += slot[33];

            den0 += __shfl_xor_sync(0xffffffffu, den0, 1);
            den0 += __shfl_xor_sync(0xffffffffu, den0, 2);
            den1 += __shfl_xor_sync(0xffffffffu, den1, 1);
            den1 += __shfl_xor_sync(0xffffffffu, den1, 2);
            const float inv0 = 1.0f / den0;
            const float inv1 = 1.0f / den1;

            float* o0 = out + (size_t)(b * NN + ibase + r0) * DD;
            float* o1 = o0 + (size_t)8 * DD;
#pragma unroll
            for (int nt = 0; nt < 8; nt++) {
                *(float2*)(o0 + nt * 8 + c0) =
                    make_float2(acc[nt].x * inv0, acc[nt].y * inv0);
                *(float2*)(o1 + nt * 8 + c0) =
                    make_float2(acc[nt].z * inv1, acc[nt].w * inv1);
            }
        }
    }
}

extern "C" void kernel_launch(void* const* d_in, const int* in_sizes, int n_in,
                              void* d_out, int out_size) {
    const float* h = nullptr;
    const int* adj = nullptr;
    const float* W = nullptr;
    const float* a = nullptr;
    for (int i = 0; i < n_in; i++) {
        const long long s = in_sizes[i];
        if (s == (long long)BB * NN * IND)      h   = (const float*)d_in[i];
        else if (s == (long long)BB * NN * NN)  adj = (const int*)d_in[i];
        else if (s == (long long)IND * DD)      W   = (const float*)d_in[i];
        else if (s == 2 * DD)                   a   = (const float*)d_in[i];
    }
    float* out = (float*)d_out;

    static bool attr_set = false;
    if (!attr_set) {
        cudaFuncSetAttribute(attn_kernel, cudaFuncAttributeMaxDynamicSharedMemorySize,
                             DSM_BYTES);
        cudaFuncSetAttribute(wh_kernel, cudaFuncAttributeMaxDynamicSharedMemorySize,
                             DSM_WH);
        attr_set = true;
    }

    wprep_kernel<<<4, 256>>>(W);
    wh_kernel<<<(BB * NN) / 128, 256, DSM_WH>>>(h, a);
    attn_kernel<<<BB * (NN / 128), 512, DSM_BYTES>>>(adj, out);
}